// round 15
// baseline (speedup 1.0000x reference)
#include <cuda_runtime.h>

// SVConvTranspose2d, round 15: R13 champion body at 64 regs -> 8 blocks/SM.
//   R13: 72 regs, 7 blocks/SM, 28 warps/SM -> 17.9 KB weight bytes in
//        flight per SM  ~= latency-BW product (17.3 KB)  -> 75% DRAM.
//   R15: 64 regs, 8 blocks/SM, 32 warps/SM -> 20.5 KB in flight, still a
//        SINGLE wave (1184 concurrent >= 1024 blocks).
// Register cut: x quads double-buffered ONE at a time (peak ~60 live)
// instead of two 2-quad sub-batches.
//
// x:      (4, 16, 128, 128) f32        -- 4 MB, L2-hot
// weight: (16, 16, 5, 5, 128, 128) f32 -- 419 MB, read EXACTLY once (ldcs)
// bias:   (1, 16, 1, 1) f32
// out:    (4, 16, 128, 128) f32
//
// out[n,o,oh,ow] = bias[o] + sum wt[i,o,kh,kw,h,w] * x[n,i,h,w],
//   h = oh+2-kh (gather), ow = w+kw-2 (scatter into acc window).
//
// Thread = (q:32 quads, o2:2 outs, ih:2 i-slices of 8); all 4 batches.
// acc[4][8] window over out positions [4q-2,4q+6): tap (kw,j) -> j+kw.
// Hot loop per (kh,i): 5 weight LDG.128 batched FIRST (5 DRAM lines in
// flight), then x pipelined one quad ahead of its FMA block.
// Grid = 128 rows x 8 o-pairs = 1024 blocks of 128 threads.

#define H_  128
#define W_  128
#define HW  16384

__global__ __launch_bounds__(128, 8)
void svct_kernel(const float* __restrict__ x,
                 const float* __restrict__ wt,
                 const float* __restrict__ bias,
                 float* __restrict__ out)
{
    __shared__ float red[2][4][2][W_];   // [o2][n][ih][w]  4 KB

    const int t   = threadIdx.x;
    const int q   = t & 31;              // quad index in row == lane
    const int o2  = (t >> 5) & 1;        // which of the 2 outs
    const int ih  = (t >> 6) & 1;        // i-slice of 8
    const int oh  = blockIdx.x >> 3;     // output row
    const int og  = blockIdx.x & 7;      // o-pair
    const int oc  = og * 2 + o2;         // output channel
    const int ibase = ih * 8;

    float acc[4][8];                     // [n][window k]
    #pragma unroll
    for (int n = 0; n < 4; n++)
        #pragma unroll
        for (int k = 0; k < 8; k++)
            acc[n][k] = 0.0f;

    #pragma unroll 1
    for (int kh = 0; kh < 5; kh++) {
        const int h = oh + 2 - kh;
        if ((unsigned)h >= (unsigned)H_) continue;

        #pragma unroll 1
        for (int ii = 0; ii < 8; ii++) {
            const int i = ibase + ii;

            // Weight batch FIRST: 5 aligned quads = 5 independent DRAM
            // lines in flight per warp. Streaming: read-once 419 MB.
            const long wrow = ((long)((i * 16 + oc) * 5 + kh) * 5) * HW + (long)h * W_;
            float4 w4[5];
            #pragma unroll
            for (int kw = 0; kw < 5; kw++)
                w4[kw] = __ldcs((const float4*)(wt + wrow + (long)kw * HW) + q);

            // x pipelined one quad ahead (L2-hot); peak regs stay ~60.
            const float4* xp = (const float4*)x + (i * H_ + h) * 32 + q;
            float4 xcur = __ldg(xp);                    // n = 0
            #pragma unroll
            for (int n = 0; n < 4; n++) {
                float4 xnext;
                if (n < 3) xnext = __ldg(xp + (n + 1) * 16 * H_ * 32);

                const float xv[4] = {xcur.x, xcur.y, xcur.z, xcur.w};
                #pragma unroll
                for (int kw = 0; kw < 5; kw++) {
                    const float wv[4] = {w4[kw].x, w4[kw].y, w4[kw].z, w4[kw].w};
                    #pragma unroll
                    for (int j = 0; j < 4; j++)
                        acc[n][j + kw] = fmaf(wv[j], xv[j], acc[n][j + kw]);
                }
                xcur = xnext;
            }
        }
    }

    // cross-lane combine (4 shuffles per n), then smem-reduce the 2 i-slices
    const bool q0  = (q == 0);
    const bool q31 = (q == 31);
    #pragma unroll
    for (int n = 0; n < 4; n++) {
        float up6 = __shfl_up_sync(0xffffffffu, acc[n][6], 1);
        float up7 = __shfl_up_sync(0xffffffffu, acc[n][7], 1);
        float dn0 = __shfl_down_sync(0xffffffffu, acc[n][0], 1);
        float dn1 = __shfl_down_sync(0xffffffffu, acc[n][1], 1);
        if (q0)  { up6 = 0.0f; up7 = 0.0f; }
        if (q31) { dn0 = 0.0f; dn1 = 0.0f; }
        *(float4*)&red[o2][n][ih][4 * q] =
            make_float4(acc[n][2] + up6, acc[n][3] + up7,
                        acc[n][4] + dn0, acc[n][5] + dn1);
    }
    __syncthreads();

    // 128 threads write 256 float4 outputs: 2 per thread
    #pragma unroll
    for (int rep = 0; rep < 2; rep++) {
        const int idx = t + rep * 128;        // (o2w:2)(nw:4)(qw:32)
        const int o2w = idx >> 7;
        const int nw  = (idx >> 5) & 3;
        const int qw  = idx & 31;
        const int ocw = og * 2 + o2w;

        float4 s0 = *(const float4*)&red[o2w][nw][0][4 * qw];
        float4 s1 = *(const float4*)&red[o2w][nw][1][4 * qw];

        const float b = __ldg(bias + ocw);
        float4 r;
        r.x = s0.x + s1.x + b;
        r.y = s0.y + s1.y + b;
        r.z = s0.z + s1.z + b;
        r.w = s0.w + s1.w + b;

        ((float4*)out)[((nw * 16 + ocw) * H_ + oh) * 32 + qw] = r;
    }
}

extern "C" void kernel_launch(void* const* d_in, const int* in_sizes, int n_in,
                              void* d_out, int out_size)
{
    const float* x    = (const float*)d_in[0];
    const float* wt   = (const float*)d_in[1];
    const float* bias = (const float*)d_in[2];
    float*       out  = (float*)d_out;

    svct_kernel<<<1024, 128>>>(x, wt, bias, out);
}

// round 16
// speedup vs baseline: 1.3043x; 1.3043x over previous
#include <cuda_runtime.h>

// SVConvTranspose2d, round 16: R13 champion + prefetch.global.L2 lookahead.
//
// R13 analysis: 28 warps/SM x 5 weight lines in flight = 17.9 KB/SM, right
// at the latency-BW product -> 75% DRAM. Registers can't go deeper (R15
// spilled at 64) and warps can't go higher (R14/R15 regressed). So add
// DRAM-level MLP with ZERO register cost: prefetch.global.L2 for the
// weight rows of iteration itr+2. DRAM->L2 then runs ~10 lines/warp ahead,
// and the register-batch LDGs become ~L2-latency hits.
//
// x:      (4, 16, 128, 128) f32        -- 4 MB, L2-hot
// weight: (16, 16, 5, 5, 128, 128) f32 -- 419 MB, read EXACTLY once
// bias:   (1, 16, 1, 1) f32
// out:    (4, 16, 128, 128) f32
//
// out[n,o,oh,ow] = bias[o] + sum wt[i,o,kh,kw,h,w] * x[n,i,h,w],
//   h = oh+2-kh (gather), ow = w+kw-2 (scatter into acc window).
//
// Thread = (q:32 quads, o2:2 outs, ih:2 i-slices of 8); all 4 batches.
// acc[4][8] window over out positions [4q-2,4q+6): tap (kw,j) -> j+kw.
// Hot loop per (kh,ii): 5 weight LDG.128 batched FIRST, prefetch itr+2's
// 5 rows (1 per 128B line, lanes q%8==0), then x in two 2-quad sub-batches.
// Grid = 1024 blocks x 128 thr; 72 regs -> 7 blocks/SM -> single wave.

#define H_  128
#define W_  128
#define HW  16384

__device__ __forceinline__ void l2_prefetch(const void* p) {
    asm volatile("prefetch.global.L2 [%0];" :: "l"(p));
}

__global__ __launch_bounds__(128, 7)
void svct_kernel(const float* __restrict__ x,
                 const float* __restrict__ wt,
                 const float* __restrict__ bias,
                 float* __restrict__ out)
{
    __shared__ float red[2][4][2][W_];   // [o2][n][ih][w]  4 KB

    const int t   = threadIdx.x;
    const int q   = t & 31;              // quad index in row == lane
    const int o2  = (t >> 5) & 1;        // which of the 2 outs
    const int ih  = (t >> 6) & 1;        // i-slice of 8
    const int oh  = blockIdx.x >> 3;     // output row
    const int og  = blockIdx.x & 7;      // o-pair
    const int oc  = og * 2 + o2;         // output channel
    const int ibase = ih * 8;

    const bool pf_lane = ((q & 7) == 0); // one prefetch per 128B line

    float acc[4][8];                     // [n][window k]
    #pragma unroll
    for (int n = 0; n < 4; n++)
        #pragma unroll
        for (int k = 0; k < 8; k++)
            acc[n][k] = 0.0f;

    #pragma unroll 1
    for (int kh = 0; kh < 5; kh++) {
        const int h = oh + 2 - kh;
        if ((unsigned)h >= (unsigned)H_) continue;

        #pragma unroll 1
        for (int ii = 0; ii < 8; ii++) {
            const int i = ibase + ii;

            // Weight batch FIRST: 5 aligned quads = 5 independent lines
            // in flight per warp. Streaming: read-once 419 MB.
            const long wrow = ((long)((i * 16 + oc) * 5 + kh) * 5) * HW + (long)h * W_;
            float4 w4[5];
            #pragma unroll
            for (int kw = 0; kw < 5; kw++)
                w4[kw] = __ldcs((const float4*)(wt + wrow + (long)kw * HW) + q);

            // L2-prefetch the weight rows of iteration itr+2 (no regs).
            {
                int ii2 = ii + 2;
                int kh2 = kh;
                if (ii2 >= 8) {
                    ii2 -= 8;
                    kh2++;
                    if ((unsigned)(oh + 2 - kh2) >= (unsigned)H_) kh2++;
                }
                if (kh2 <= 4 && (unsigned)(oh + 2 - kh2) < (unsigned)H_) {
                    const int i2 = ibase + ii2;
                    const int h2 = oh + 2 - kh2;
                    const float* wr2 = wt + ((long)((i2 * 16 + oc) * 5 + kh2) * 5) * HW
                                          + (long)h2 * W_;
                    if (pf_lane) {
                        #pragma unroll
                        for (int kw = 0; kw < 5; kw++)
                            l2_prefetch((const float4*)(wr2 + (long)kw * HW) + q);
                    }
                }
            }

            // x in two 2-quad sub-batches (L2-hot), peak regs ~72.
            #pragma unroll
            for (int half = 0; half < 2; half++) {
                float4 xq[2];
                #pragma unroll
                for (int m = 0; m < 2; m++)
                    xq[m] = __ldg((const float4*)x
                                  + (((half * 2 + m) * 16 + i) * H_ + h) * 32 + q);

                #pragma unroll
                for (int kw = 0; kw < 5; kw++) {
                    const float wv[4] = {w4[kw].x, w4[kw].y, w4[kw].z, w4[kw].w};
                    #pragma unroll
                    for (int m = 0; m < 2; m++) {
                        const int n = half * 2 + m;
                        const float xv[4] = {xq[m].x, xq[m].y, xq[m].z, xq[m].w};
                        #pragma unroll
                        for (int j = 0; j < 4; j++)
                            acc[n][j + kw] = fmaf(wv[j], xv[j], acc[n][j + kw]);
                    }
                }
            }
        }
    }

    // cross-lane combine (4 shuffles per n), then smem-reduce the 2 i-slices
    const bool q0  = (q == 0);
    const bool q31 = (q == 31);
    #pragma unroll
    for (int n = 0; n < 4; n++) {
        float up6 = __shfl_up_sync(0xffffffffu, acc[n][6], 1);
        float up7 = __shfl_up_sync(0xffffffffu, acc[n][7], 1);
        float dn0 = __shfl_down_sync(0xffffffffu, acc[n][0], 1);
        float dn1 = __shfl_down_sync(0xffffffffu, acc[n][1], 1);
        if (q0)  { up6 = 0.0f; up7 = 0.0f; }
        if (q31) { dn0 = 0.0f; dn1 = 0.0f; }
        *(float4*)&red[o2][n][ih][4 * q] =
            make_float4(acc[n][2] + up6, acc[n][3] + up7,
                        acc[n][4] + dn0, acc[n][5] + dn1);
    }
    __syncthreads();

    // 128 threads write 256 float4 outputs: 2 per thread
    #pragma unroll
    for (int rep = 0; rep < 2; rep++) {
        const int idx = t + rep * 128;        // (o2w:2)(nw:4)(qw:32)
        const int o2w = idx >> 7;
        const int nw  = (idx >> 5) & 3;
        const int qw  = idx & 31;
        const int ocw = og * 2 + o2w;

        float4 s0 = *(const float4*)&red[o2w][nw][0][4 * qw];
        float4 s1 = *(const float4*)&red[o2w][nw][1][4 * qw];

        const float b = __ldg(bias + ocw);
        float4 r;
        r.x = s0.x + s1.x + b;
        r.y = s0.y + s1.y + b;
        r.z = s0.z + s1.z + b;
        r.w = s0.w + s1.w + b;

        ((float4*)out)[((nw * 16 + ocw) * H_ + oh) * 32 + qw] = r;
    }
}

extern "C" void kernel_launch(void* const* d_in, const int* in_sizes, int n_in,
                              void* d_out, int out_size)
{
    const float* x    = (const float*)d_in[0];
    const float* wt   = (const float*)d_in[1];
    const float* bias = (const float*)d_in[2];
    float*       out  = (float*)d_out;

    svct_kernel<<<1024, 128>>>(x, wt, bias, out);
}